// round 17
// baseline (speedup 1.0000x reference)
#include <cuda_runtime.h>
#include <cuda.h>
#include <cstdint>
#include <dlfcn.h>

#define S_SUBJ   4
#define B_BATCH  64
#define K_VOX    40000
#define OUT_DIMN 768
#define V_VOX    (64*64*48)

#define OT      96           // outputs per block tile
#define KSPLIT  50
#define KCHUNK  800          // 40000 / 50
#define KC      32           // K per smem chunk (128B rows -> SW128 max)
#define NITER   (KCHUNK/KC)  // 25

// ---- TMA kernel: MT=32 samples per tile, dense SW128, 128B row pitch ----
#define TMT       32
#define T_STAGES  4          // depth-3 pipeline
#define T_WBYTES  (OT*128)             // 12288
#define T_STAGE_B (T_WBYTES + TMT*128) // 16384
#define T_SMEM    (T_STAGES*T_STAGE_B + 1024)   // 66560 -> 3 blocks/SM

// ---- fallback (LDGSTS, R14 config: MT=16) ----
#define FMT     16
#define WSTRIDE 36
#define WS_F    (OT*WSTRIDE)
#define GS_F    (FMT*WSTRIDE)
#define STAGE_F (WS_F+GS_F)
#define STAGE_B (STAGE_F*4)
#define F_STAGES 4
#define F_SMEM  (F_STAGES*STAGE_B)

// -------- device scratch (allocation-free per harness rules) --------
__device__ __align__(256) float g_G[(size_t)B_BATCH * K_VOX];
__device__ int   g_subj[B_BATCH];
__device__ int   g_order[B_BATCH];
__device__ int   g_slotsubj[B_BATCH];
__device__ int   g_off[S_SUBJ + 1];

// -------- 1) grouping + dtype detection --------
__global__ void setup_kernel(const void* idp) {
    __shared__ int sh_id64[B_BATCH], sh_id32[B_BATCH];
    __shared__ int sh_is64;
    const int* w = (const int*)idp;
    int t = threadIdx.x;          // 64 threads
    sh_id64[t] = w[2 * t];
    sh_id32[t] = w[t];
    int hi = w[2 * t + 1];
    unsigned any = __ballot_sync(0xffffffffu, hi != 0);
    if (t == 0) sh_is64 = 1;
    __syncthreads();
    if (any != 0) sh_is64 = 0;
    __syncthreads();
    g_subj[t] = sh_is64 ? sh_id64[t] : sh_id32[t];
    __syncthreads();
    if (t == 0) {
        int cnt[S_SUBJ];
        for (int i = 0; i < S_SUBJ; i++) cnt[i] = 0;
        for (int b = 0; b < B_BATCH; b++)
            cnt[sh_is64 ? sh_id64[b] : sh_id32[b]]++;
        int off = 0, pos[S_SUBJ];
        for (int i = 0; i < S_SUBJ; i++) { g_off[i] = off; pos[i] = off; off += cnt[i]; }
        g_off[S_SUBJ] = off;
        for (int b = 0; b < B_BATCH; b++) {
            int sb = sh_is64 ? sh_id64[b] : sh_id32[b];
            int p = pos[sb]++;
            g_order[p] = b;
            g_slotsubj[p] = sb;
        }
    }
}

// -------- 2) out = bias[subj[b]] --------
__global__ void init_out_kernel(float* out, const float* bias) {
    int i = blockIdx.x * blockDim.x + threadIdx.x;
    if (i >= B_BATCH * OUT_DIMN) return;
    int b = i / OUT_DIMN;
    int o = i - b * OUT_DIMN;
    out[i] = bias[g_subj[b] * OUT_DIMN + o];
}

// -------- 3) gather x4 (pre-rounds G to tf32-RNA) --------
__global__ void gather_kernel(const float* __restrict__ fmri, const int* __restrict__ idx) {
    int slot = blockIdx.y;
    int k4 = blockIdx.x * blockDim.x + threadIdx.x;
    if (k4 >= K_VOX / 4) return;
    int b = g_order[slot];
    int s = g_slotsubj[slot];
    int4 iv = *(const int4*)(idx + s * K_VOX + k4 * 4);
    const float* f = fmri + (size_t)b * V_VOX;
    float v0 = f[iv.x], v1 = f[iv.y], v2 = f[iv.z], v3 = f[iv.w];
    uint4 o;
    asm("cvt.rna.tf32.f32 %0, %1;" : "=r"(o.x) : "f"(v0));
    asm("cvt.rna.tf32.f32 %0, %1;" : "=r"(o.y) : "f"(v1));
    asm("cvt.rna.tf32.f32 %0, %1;" : "=r"(o.z) : "f"(v2));
    asm("cvt.rna.tf32.f32 %0, %1;" : "=r"(o.w) : "f"(v3));
    *(uint4*)(g_G + (size_t)slot * K_VOX + k4 * 4) = o;
}

// -------- asm helpers --------
__device__ __forceinline__ uint32_t smem_u32(const void* p) {
    uint32_t a;
    asm("{ .reg .u64 t; cvta.to.shared.u64 t, %1; cvt.u32.u64 %0, t; }" : "=r"(a) : "l"(p));
    return a;
}
__device__ __forceinline__ void cp_async16(uint32_t smem_addr, const void* gptr) {
    asm volatile("cp.async.cg.shared.global [%0], [%1], 16;" :: "r"(smem_addr), "l"(gptr));
}
__device__ __forceinline__ void cp_commit() { asm volatile("cp.async.commit_group;"); }
__device__ __forceinline__ void cp_wait2() { asm volatile("cp.async.wait_group 2;"); }
__device__ __forceinline__ void cp_wait1() { asm volatile("cp.async.wait_group 1;"); }
__device__ __forceinline__ void cp_wait0() { asm volatile("cp.async.wait_group 0;"); }
__device__ __forceinline__ void mbar_init(uint32_t a, uint32_t c) {
    asm volatile("mbarrier.init.shared.b64 [%0], %1;" :: "r"(a), "r"(c) : "memory");
}
__device__ __forceinline__ void mbar_expect(uint32_t a, uint32_t bytes) {
    asm volatile("mbarrier.arrive.expect_tx.shared.b64 _, [%0], %1;"
                 :: "r"(a), "r"(bytes) : "memory");
}
__device__ __forceinline__ void mbar_wait(uint32_t a, int parity) {
    asm volatile(
        "{\n\t.reg .pred P;\n\t"
        "W_%=:\n\t"
        "mbarrier.try_wait.parity.acquire.cta.shared::cta.b64 P, [%0], %1, 0x989680;\n\t"
        "@!P bra W_%=;\n\t}"
        :: "r"(a), "r"(parity) : "memory");
}
__device__ __forceinline__ void tma2d(uint32_t dst, const void* map, int x, int y,
                                      uint32_t mbar) {
    asm volatile(
        "cp.async.bulk.tensor.2d.shared::cta.global.tile.mbarrier::complete_tx::bytes "
        "[%0], [%1, {%2, %3}], [%4];"
        :: "r"(dst), "l"(map), "r"(x), "r"(y), "r"(mbar) : "memory");
}
__device__ __forceinline__ uint32_t lds_u(uint32_t a) {
    uint32_t v;
    asm volatile("ld.shared.b32 %0, [%1];" : "=r"(v) : "r"(a));
    return v;
}
__device__ __forceinline__ uint32_t tf32_rna(float f) {
    uint32_t r;
    asm("cvt.rna.tf32.f32 %0, %1;" : "=r"(r) : "f"(f));
    return r;
}
__device__ __forceinline__ void mma_tf32(float* c, uint32_t a0, uint32_t a1,
                                         uint32_t a2, uint32_t a3,
                                         uint32_t b0, uint32_t b1) {
    asm volatile(
        "mma.sync.aligned.m16n8k8.row.col.f32.tf32.tf32.f32 "
        "{%0,%1,%2,%3}, {%4,%5,%6,%7}, {%8,%9}, {%0,%1,%2,%3};"
        : "+f"(c[0]), "+f"(c[1]), "+f"(c[2]), "+f"(c[3])
        : "r"(a0), "r"(a1), "r"(a2), "r"(a3), "r"(b0), "r"(b1));
}

// -------- 4a) TMA-fed GEMM (mma.sync tf32), MT=32 --------
__global__ void __launch_bounds__(256, 3) gemm_tma(
    const __grid_constant__ CUtensorMap wmap,
    const __grid_constant__ CUtensorMap gmap,
    float* __restrict__ out) {
    extern __shared__ __align__(16) char dsm[];
    __shared__ __align__(16) unsigned long long s_mbar[T_STAGES];

    int tid = threadIdx.x;
    int warp = tid >> 5;
    int lane = tid & 31;

    int s = blockIdx.y >> 1;
    int mtile = (blockIdx.y & 1) * TMT;
    int off = g_off[s];
    int count = g_off[s + 1] - off;
    int rows = count - mtile;
    if (rows <= 0) return;
    if (rows > TMT) rows = TMT;

    int otile = blockIdx.x * OT;
    int k0 = blockIdx.z * KCHUNK;

    uint32_t base = (smem_u32(dsm) + 1023u) & ~1023u;   // 1024-align for SW128
    uint32_t mb0 = smem_u32(&s_mbar[0]);
    if (tid < T_STAGES) mbar_init(mb0 + tid * 8, 1);
    __syncthreads();

    int wrow = s * OUT_DIMN + otile;
    int grow = off + mtile;      // OOB rows zero-filled by TMA

#define TISSUE(IT, ST)                                                         \
    do {                                                                       \
        if (tid == 0) {                                                        \
            uint32_t mb = mb0 + (ST) * 8;                                      \
            mbar_expect(mb, T_STAGE_B);                                        \
            tma2d(base + (ST) * T_STAGE_B, &wmap, k0 + (IT) * KC, wrow, mb);   \
            tma2d(base + (ST) * T_STAGE_B + T_WBYTES, &gmap,                   \
                  k0 + (IT) * KC, grow, mb);                                   \
        }                                                                      \
    } while (0)

    TISSUE(0, 0); TISSUE(1, 1); TISSUE(2, 2);

    int ohalf = (warp & 1) * 48;
    int kq = warp >> 1;
    int lg = lane >> 2;
    int lt = lane & 3;
    // swizzled in-row byte offsets (row&7 == lg for every row we touch)
    uint32_t off0 = ((uint32_t)((2 * kq) ^ lg) << 4) + lt * 4;
    uint32_t off1 = ((uint32_t)((2 * kq + 1) ^ lg) << 4) + lt * 4;

    float acc[2][6][4];
#pragma unroll
    for (int h = 0; h < 2; h++)
#pragma unroll
        for (int j = 0; j < 6; j++)
#pragma unroll
            for (int r = 0; r < 4; r++) acc[h][j][r] = 0.f;

    int st = 0, wst = 3;
    for (int it = 0; it < NITER; it++) {
        __syncthreads();                 // gates stage reuse (compute it-1 done)
        if (it + 3 < NITER) {
            TISSUE(it + 3, wst);
            wst = (wst == T_STAGES - 1) ? 0 : wst + 1;
        }
        mbar_wait(mb0 + st * 8, (it / T_STAGES) & 1);

        uint32_t wb_ = base + st * T_STAGE_B;
        uint32_t gb_ = wb_ + T_WBYTES;
        st = (st == T_STAGES - 1) ? 0 : st + 1;

        uint32_t a0 = lds_u(gb_ + lg * 128 + off0);
        uint32_t a1 = lds_u(gb_ + (lg + 8) * 128 + off0);
        uint32_t a2 = lds_u(gb_ + lg * 128 + off1);
        uint32_t a3 = lds_u(gb_ + (lg + 8) * 128 + off1);
        uint32_t a4 = lds_u(gb_ + (lg + 16) * 128 + off0);
        uint32_t a5 = lds_u(gb_ + (lg + 24) * 128 + off0);
        uint32_t a6 = lds_u(gb_ + (lg + 16) * 128 + off1);
        uint32_t a7 = lds_u(gb_ + (lg + 24) * 128 + off1);
#pragma unroll
        for (int j = 0; j < 6; j++) {
            uint32_t wr = wb_ + (ohalf + lg + 8 * j) * 128;
            // +0x1000 then HMMA truncation == cvt.rna.tf32 (finite inputs)
            uint32_t b0 = lds_u(wr + off0) + 0x1000u;
            uint32_t b1 = lds_u(wr + off1) + 0x1000u;
            mma_tf32(acc[0][j], a0, a1, a2, a3, b0, b1);
            mma_tf32(acc[1][j], a4, a5, a6, a7, b0, b1);
        }
    }
#undef TISSUE

    // ---- kq reduction in smem, then atomics ----
    __syncthreads();
    const int RS = 100;
    float* red = (float*)(((uintptr_t)dsm + 1023) & ~(uintptr_t)1023);
#pragma unroll
    for (int h = 0; h < 2; h++)
#pragma unroll
        for (int j = 0; j < 6; j++) {
            int o = ohalf + j * 8 + lt * 2;
            float* r0 = &red[(kq * TMT + h * 16 + lg) * RS + o];
            r0[0] = acc[h][j][0];
            r0[1] = acc[h][j][1];
            r0[8 * RS] = acc[h][j][2];
            r0[8 * RS + 1] = acc[h][j][3];
        }
    __syncthreads();
    int rm = tid >> 3;            // 0..31
    int oc = (tid & 7) * 12;      // 12 outputs per thread
    if (rm < rows) {
        float sum[12];
#pragma unroll
        for (int i = 0; i < 12; i++) sum[i] = 0.f;
#pragma unroll
        for (int q = 0; q < 4; q++) {
            const float* rp = &red[(q * TMT + rm) * RS + oc];
#pragma unroll
            for (int i = 0; i < 12; i++) sum[i] += rp[i];
        }
        int b = g_order[off + mtile + rm];
        float* op = &out[b * OUT_DIMN + otile + oc];
#pragma unroll
        for (int i = 0; i < 12; i++) atomicAdd(op + i, sum[i]);
    }
}

// -------- 4b) fallback: LDGSTS-fed GEMM (R14, MT=16) --------
__global__ void __launch_bounds__(256, 3) gemm_fb(const float* __restrict__ Wt,
                                                  float* __restrict__ out) {
    extern __shared__ __align__(16) float smem[];

    int tid = threadIdx.x;
    int warp = tid >> 5;
    int lane = tid & 31;

    int s = blockIdx.y >> 2;
    int mtile = (blockIdx.y & 3) * FMT;
    int off = g_off[s];
    int count = g_off[s + 1] - off;
    int rows = count - mtile;
    if (rows <= 0) return;
    if (rows > FMT) rows = FMT;

    int otile = blockIdx.x * OT;
    size_t k0 = (size_t)blockIdx.z * KCHUNK;

    uint32_t smem_b = smem_u32(smem);

    int cell = tid & 7;
    int rb = tid >> 3;
    const float* wbase = Wt + (size_t)(s * OUT_DIMN + otile + rb) * K_VOX + k0 + cell * 4;
    int mglob = mtile + rb;
    int slot = off + (mglob < count ? mglob : count - 1);
    const float* gbase = g_G + (size_t)slot * K_VOX + k0 + cell * 4;
    uint32_t wdoff = rb * (WSTRIDE * 4) + cell * 16;

    int ohalf = (warp & 1) * 48;
    int kq = warp >> 1;
    int lg = lane >> 2;
    int lt = lane & 3;

    float acc[6][4];
#pragma unroll
    for (int j = 0; j < 6; j++)
#pragma unroll
        for (int r = 0; r < 4; r++) acc[j][r] = 0.f;

#define ISSUE(IT, ST)                                                          \
    do {                                                                       \
        uint32_t wsb = smem_b + (ST) * STAGE_B;                                \
        const float* wsrc = wbase + (IT) * KC;                                 \
        _Pragma("unroll")                                                      \
        for (int q = 0; q < 3; q++)                                            \
            cp_async16(wsb + wdoff + q * (32 * WSTRIDE * 4),                   \
                       wsrc + (size_t)(32 * q) * K_VOX);                       \
        if (rb < FMT)                                                          \
            cp_async16(wsb + WS_F * 4 + wdoff, gbase + (IT) * KC);             \
        cp_commit();                                                           \
    } while (0)

    ISSUE(0, 0); ISSUE(1, 1); ISSUE(2, 2);

    int st = 0, wst = 3;
    for (int it = 0; it < NITER; it++) {
        if (it + 3 <= NITER)      cp_wait2();
        else if (it + 2 <= NITER) cp_wait1();
        else                      cp_wait0();
        __syncthreads();
        if (it + 3 < NITER) {
            ISSUE(it + 3, wst);
            wst = (wst == F_STAGES - 1) ? 0 : wst + 1;
        }

        const float* ws = smem + st * STAGE_F;
        const float* gs = ws + WS_F;
        st = (st == F_STAGES - 1) ? 0 : st + 1;

        int kb = kq * 8 + lt;
        const float* ga = &gs[lg * WSTRIDE + kb];
        uint32_t a0 = __float_as_uint(ga[0]);
        uint32_t a1 = __float_as_uint(ga[8 * WSTRIDE]);
        uint32_t a2 = __float_as_uint(ga[4]);
        uint32_t a3 = __float_as_uint(ga[8 * WSTRIDE + 4]);
        const float* wb = &ws[(ohalf + lg) * WSTRIDE + kb];
#pragma unroll
        for (int j = 0; j < 6; j++) {
            uint32_t b0 = tf32_rna(wb[j * 8 * WSTRIDE]);
            uint32_t b1 = tf32_rna(wb[j * 8 * WSTRIDE + 4]);
            mma_tf32(acc[j], a0, a1, a2, a3, b0, b1);
        }
    }
#undef ISSUE

    __syncthreads();
    const int RS = 100;
    float* red = smem;
#pragma unroll
    for (int j = 0; j < 6; j++) {
        int o = ohalf + j * 8 + lt * 2;
        float* r0 = &red[(kq * FMT + lg) * RS + o];
        r0[0] = acc[j][0];
        r0[1] = acc[j][1];
        r0[8 * RS] = acc[j][2];
        r0[8 * RS + 1] = acc[j][3];
    }
    __syncthreads();
    int rm = tid >> 4;
    int oc = (tid & 15) * 6;
    if (rm < rows) {
        float sum[6];
#pragma unroll
        for (int i = 0; i < 6; i++) sum[i] = 0.f;
#pragma unroll
        for (int q = 0; q < 4; q++) {
            const float* rp = &red[(q * FMT + rm) * RS + oc];
#pragma unroll
            for (int i = 0; i < 6; i++) sum[i] += rp[i];
        }
        int b = g_order[off + mtile + rm];
        float* op = &out[b * OUT_DIMN + otile + oc];
#pragma unroll
        for (int i = 0; i < 6; i++) atomicAdd(op + i, sum[i]);
    }
}

// -------- host --------
typedef CUresult (*EncodeFn)(CUtensorMap*, CUtensorMapDataType, cuuint32_t, void*,
                             const cuuint64_t*, const cuuint64_t*, const cuuint32_t*,
                             const cuuint32_t*, CUtensorMapInterleave,
                             CUtensorMapSwizzle, CUtensorMapL2promotion,
                             CUtensorMapFloatOOBfill);

extern "C" void kernel_launch(void* const* d_in, const int* in_sizes, int n_in,
                              void* d_out, int out_size) {
    (void)in_sizes; (void)n_in; (void)out_size;
    const void*  idp  = d_in[0];
    const float* fmri = (const float*)d_in[1];
    const int*   idx  = (const int*)d_in[2];
    const float* Wt   = (const float*)d_in[3];
    const float* bias = (const float*)d_in[4];
    float* out = (float*)d_out;

    static int inited = 0;
    static EncodeFn enc = nullptr;
    if (!inited) {
        inited = 1;
        void* h = dlopen("libcuda.so.1", RTLD_LAZY | RTLD_GLOBAL);
        if (h) enc = (EncodeFn)dlsym(h, "cuTensorMapEncodeTiled");
        cudaFuncSetAttribute(gemm_tma, cudaFuncAttributeMaxDynamicSharedMemorySize, T_SMEM);
        cudaFuncSetAttribute(gemm_fb, cudaFuncAttributeMaxDynamicSharedMemorySize, F_SMEM);
    }

    setup_kernel<<<1, 64>>>(idp);
    init_out_kernel<<<(B_BATCH * OUT_DIMN + 255) / 256, 256>>>(out, bias);
    gather_kernel<<<dim3((K_VOX / 4 + 255) / 256, B_BATCH), 256>>>(fmri, idx);

    bool tma_ok = false;
    if (enc) {
        void* gptr = nullptr;
        cudaGetSymbolAddress(&gptr, g_G);
        CUtensorMap wmap, gmap;
        cuuint64_t wdims[2] = {K_VOX, (cuuint64_t)S_SUBJ * OUT_DIMN};
        cuuint64_t gdims[2] = {K_VOX, B_BATCH};
        cuuint64_t strides[1] = {(cuuint64_t)K_VOX * 4};
        cuuint32_t wbox[2] = {KC, OT};
        cuuint32_t gbox[2] = {KC, TMT};
        cuuint32_t estr[2] = {1, 1};
        CUresult r1 = enc(&wmap, CU_TENSOR_MAP_DATA_TYPE_FLOAT32, 2, (void*)Wt,
                          wdims, strides, wbox, estr, CU_TENSOR_MAP_INTERLEAVE_NONE,
                          CU_TENSOR_MAP_SWIZZLE_128B, CU_TENSOR_MAP_L2_PROMOTION_L2_128B,
                          CU_TENSOR_MAP_FLOAT_OOB_FILL_NONE);
        CUresult r2 = enc(&gmap, CU_TENSOR_MAP_DATA_TYPE_FLOAT32, 2, gptr,
                          gdims, strides, gbox, estr, CU_TENSOR_MAP_INTERLEAVE_NONE,
                          CU_TENSOR_MAP_SWIZZLE_128B, CU_TENSOR_MAP_L2_PROMOTION_L2_128B,
                          CU_TENSOR_MAP_FLOAT_OOB_FILL_NONE);
        if (r1 == CUDA_SUCCESS && r2 == CUDA_SUCCESS) {
            gemm_tma<<<dim3(OUT_DIMN / OT, 8, KSPLIT), 256, T_SMEM>>>(wmap, gmap, out);
            tma_ok = true;
        }
    }
    if (!tma_ok) {
        gemm_fb<<<dim3(OUT_DIMN / OT, 16, KSPLIT), 256, F_SMEM>>>(Wt, out);
    }
}